// round 17
// baseline (speedup 1.0000x reference)
#include <cuda_runtime.h>
#include <cuda_bf16.h>
#include <cstdint>

// ===========================================================================
// MoE AG-scatter grouped GEMM via single-pass TF32 mma.sync.
//   out[s,:] = x[token(s),:] @ W[e(s),:,:]^T      (fp32 in/out)
// R17 = R16 numerics (raw fp32 both sides, HW tf32 truncation, epilogue
//   FMUL x1.000704 bias cancel, rel_err 3.09e-4) with the cp.async storm
//   (2176 x 16B per CTA-chunk, ~64% of all issued instructions) replaced by
//   cp.async.bulk (sm_90 baseline PTX, valid on plain sm_103): each thread
//   issues ONE 128B row copy per stage (256 total), completion via per-stage
//   mbarrier with per-thread arrive.expect_tx(128) (count=256 -> no early-
//   delivery race). A's XOR swizzle is replaced by the 144B-stride trick
//   (9*16 stride => ldmatrix banks (r+c) mod 8, conflict-free on LINEAR rows)
//   so bulk rows can be contiguous. Buffer-reuse safety keeps the single
//   __syncthreads per chunk (reads of stage (c+2)%3 finished at chunk c-1).
// Pipeline: BK=32 (4 tf32 k-steps), 3 stages, mid-chunk load issue, CTA
// 128x128, 8 warps 4Mx2N, ldmatrix-b16-on-fp32 A/B fragments, 2 CTAs/SM,
// persistent job loop. Prep = token map + tile table only.
// ===========================================================================

#define NTOK   8192
#define TOPK   2
#define MTOT   (NTOK * TOPK)          // 16384
#define NDIM   1024
#define KDIM   1024
#define NEXP   8

#define BM     128
#define BN     128
#define BK     32                     // fp32 k per chunk = 4 tf32 k-steps
#define NCHUNK (KDIM / BK)            // 32
#define NSTAGE 3
#define NBLK   (NDIM / BN)            // 8
#define MAXTILES (MTOT / BM + NEXP)   // 136

#define ASTRIDE 144                   // 9*16: linear rows, ldsm conflict-free
#define BSTRIDE 144
#define OFF_B   (128 * ASTRIDE)       // 18432
#define STAGE_BYTES (2 * 128 * 144)   // 36864
#define TOK_OFF (NSTAGE * STAGE_BYTES)         // 110592
#define SMEM_TOTAL (TOK_OFF + 512 + 16 + 32)   // 111152

// epilogue compensation for two-sided tf32 truncation
#define OSCALE 1.000704f

// ---------------- device-global scratch ------------------------------------
__device__ int g_token_of_row[MTOT];
__device__ int g_tile_e[MAXTILES];
__device__ int g_tile_row0[MAXTILES];
__device__ int g_tile_rows[MAXTILES];
__device__ int g_njobs;
__device__ int g_job;

// ---------------- helpers ---------------------------------------------------
__device__ __forceinline__ uint32_t smem_to_u32(const void* p) {
    uint32_t a;
    asm("{ .reg .u64 t; cvta.to.shared.u64 t, %1; cvt.u32.u64 %0, t; }"
        : "=r"(a) : "l"(p));
    return a;
}

#define MBARRIER_INIT(mbar, cnt) \
    asm volatile("mbarrier.init.shared.b64 [%0], %1;" \
        :: "r"((uint32_t)(mbar)), "r"((uint32_t)(cnt)) : "memory")

#define MBAR_EXPECT_TX(mbar, bytes) \
    asm volatile("mbarrier.arrive.expect_tx.shared.b64 _, [%0], %1;" \
        :: "r"((uint32_t)(mbar)), "r"((uint32_t)(bytes)) : "memory")

#define BULK128(dst_u32, src_ptr, mbar) \
    asm volatile("cp.async.bulk.shared::cta.global.mbarrier::complete_tx::bytes " \
        "[%0], [%1], 128, [%2];" \
        :: "r"(dst_u32), "l"(src_ptr), "r"((uint32_t)(mbar)) : "memory")

#define MBARRIER_WAIT_PARITY(mbar_smem_addr, phase_parity) do { \
    uint32_t _mbar = (uint32_t)(mbar_smem_addr); \
    uint32_t _parity = (uint32_t)(phase_parity); \
    uint32_t _done; \
    asm volatile( \
        "{ .reg .pred p;\n\t" \
        "mbarrier.try_wait.parity.acquire.cta.shared::cta.b64 p, [%1], %2;\n\t" \
        "selp.b32 %0, 1, 0, p; }" \
        : "=r"(_done) : "r"(_mbar), "r"(_parity) : "memory"); \
    if (!_done) { \
        asm volatile( \
            "{ .reg .pred P1;\n\t" \
            "WAIT_LOOP_%=:\n\t" \
            "mbarrier.try_wait.parity.acquire.cta.shared::cta.b64 P1, [%0], %1, 0x989680;\n\t" \
            "@P1 bra.uni WAIT_DONE_%=;\n\t" \
            "bra.uni WAIT_LOOP_%=;\n\t" \
            "WAIT_DONE_%=: }" \
            :: "r"(_mbar), "r"(_parity) : "memory"); \
    } \
} while (0)

__device__ __forceinline__ void ldsm_x4(uint32_t r[4], uint32_t addr) {
    asm volatile("ldmatrix.sync.aligned.m8n8.x4.shared.b16 {%0,%1,%2,%3}, [%4];"
        : "=r"(r[0]), "=r"(r[1]), "=r"(r[2]), "=r"(r[3]) : "r"(addr));
}

__device__ __forceinline__ void mma_tf32(float d[4],
    const uint32_t a[4], uint32_t b0, uint32_t b1)
{
    asm volatile(
        "mma.sync.aligned.m16n8k8.row.col.f32.tf32.tf32.f32 "
        "{%0,%1,%2,%3}, {%4,%5,%6,%7}, {%8,%9}, {%0,%1,%2,%3};"
        : "+f"(d[0]), "+f"(d[1]), "+f"(d[2]), "+f"(d[3])
        : "r"(a[0]), "r"(a[1]), "r"(a[2]), "r"(a[3]), "r"(b0), "r"(b1));
}

// ---------------- tiny prep: token map + tile table only --------------------
#define MBLK (MTOT / 256)             // 64
#define PREP_GRID (MBLK + 1)

__global__ __launch_bounds__(256) void prep_all(
    const int* __restrict__ scatter, const int* __restrict__ splits)
{
    int b = blockIdx.x;
    if (b < MBLK) {
        int f = b * 256 + threadIdx.x;
        g_token_of_row[scatter[f]] = f / TOPK;
    } else if (threadIdx.x == 0) {
        int cum = 0, t = 0;
        for (int e = 0; e < NEXP; e++) {
            int cnt = splits[e];
            for (int r0 = 0; r0 < cnt; r0 += BM) {
                g_tile_e[t] = e;
                g_tile_row0[t] = cum + r0;
                g_tile_rows[t] = (cnt - r0 < BM) ? (cnt - r0) : BM;
                t++;
            }
            cum += cnt;
        }
        g_njobs = t * NBLK;
        g_job = 0;
    }
}

// ---------------- main GEMM --------------------------------------------------
// One stage load: each thread issues ONE 128B bulk copy (A row or B row).
__device__ __forceinline__ void load_stage(uint32_t sbuf, int c,
                                           const float* __restrict__ x,
                                           const float* __restrict__ w,
                                           int wbase, const int* s_tok,
                                           int tid, uint32_t mbar)
{
    const size_t kb = (size_t)c * BK;
    const char* src;
    uint32_t dst;
    if (tid < 128) {                     // A row (gathered raw fp32 x)
        dst = sbuf + (uint32_t)(tid * ASTRIDE);
        src = (const char*)(x + (size_t)s_tok[tid] * KDIM + kb);
    } else {                             // B row (raw fp32 W)
        int n = tid - 128;
        dst = sbuf + OFF_B + (uint32_t)(n * BSTRIDE);
        src = (const char*)(w + (size_t)(wbase + n) * KDIM + kb);
    }
    MBAR_EXPECT_TX(mbar, 128);
    BULK128(dst, src, mbar);
}

__global__ __launch_bounds__(256, 2) void moe_gemm_tf32(
    const float* __restrict__ x, const float* __restrict__ w,
    float* __restrict__ out)
{
    extern __shared__ char smem_raw[];
    const uint32_t stage0 = smem_to_u32(smem_raw);
    int* s_tok = (int*)(smem_raw + TOK_OFF);
    int* s_job = (int*)(smem_raw + TOK_OFF + 512);
    const uint32_t mbar0 = stage0 + TOK_OFF + 512 + 16;
    #define FULLB(s) (mbar0 + (uint32_t)(s) * 8u)

    const int tid  = threadIdx.x;
    const int wid  = tid >> 5;
    const int lane = tid & 31;
    const int wm   = wid & 3;          // 4 warps along M (32 rows each)
    const int wn   = wid >> 2;         // 2 warps along N (64 cols each)

    if (tid == 0) {
        MBARRIER_INIT(FULLB(0), 256);
        MBARRIER_INIT(FULLB(1), 256);
        MBARRIER_INIT(FULLB(2), 256);
    }

    // ---- A fragment addressing (linear 144B rows; banks (r+c) mod 8) ----
    const int aq   = (lane >> 3) & 1;              // +8 rows for matrices 1,3
    const int skA  = lane >> 4;                    // +1 seg (k+4) for mats 2,3
    uint32_t baseA[2];
    #pragma unroll
    for (int mt = 0; mt < 2; mt++) {
        int r = wm * 32 + mt * 16 + aq * 8 + (lane & 7);
        baseA[mt] = (uint32_t)(r * ASTRIDE);
    }
    // ---- B fragment addressing (unchanged) ----
    const int bg   = lane >> 3;                    // matrix group 0..3
    const uint32_t baseB = (uint32_t)(
        (wn * 64 + ((bg >> 1) ? 8 : 0) + (lane & 7)) * BSTRIDE + (bg & 1) * 16);

    const int njobs = g_njobs;
    int jc = 0;                                    // per-CTA job counter

    while (true) {
        __syncthreads();                 // smem + mbar init visible / job reuse
        if (tid == 0) *s_job = atomicAdd(&g_job, 1);
        __syncthreads();
        const int job = *s_job;
        if (job >= njobs) break;

        const int tile = job >> 3;                 // NBLK = 8
        const int nb   = job & 7;
        const int nrows = g_tile_rows[tile];
        const int row0  = g_tile_row0[tile];
        const int e     = g_tile_e[tile];
        const int n0    = nb * BN;
        const int wbase = e * NDIM + n0;

        if (tid < 128)
            s_tok[tid] = (tid < nrows) ? g_token_of_row[row0 + tid] : 0;
        __syncthreads();

        float acc[2][8][4];
        #pragma unroll
        for (int mt = 0; mt < 2; mt++)
            #pragma unroll
            for (int nt = 0; nt < 8; nt++)
                #pragma unroll
                for (int q = 0; q < 4; q++)
                    acc[mt][nt][q] = 0.0f;

        // continuous stage rotation across jobs
        const int gc0 = jc * NCHUNK;
        int cs = gc0 % 3;                          // current stage
        int cu = (gc0 / 3) & 1;                    // current full-phase parity

        // prologue: stages for chunks 0 and 1
        {
            int s1 = (cs + 1 == 3) ? 0 : cs + 1;
            load_stage(stage0 + cs * STAGE_BYTES, 0, x, w, wbase, s_tok, tid, FULLB(cs));
            load_stage(stage0 + s1 * STAGE_BYTES, 1, x, w, wbase, s_tok, tid, FULLB(s1));
        }

        for (int c = 0; c < NCHUNK; c++) {
            const uint32_t sbuf = stage0 + cs * STAGE_BYTES;
            __syncthreads();               // reads of stage (cs+2)%3 are done
            MBARRIER_WAIT_PARITY(FULLB(cs), cu);

            #pragma unroll
            for (int ks = 0; ks < 4; ks++) {
                // mid-chunk: fill stage (cs+2)%3 for chunk c+2
                if (ks == 2 && c + 2 < NCHUNK) {
                    int t = cs + 2; if (t >= 3) t -= 3;
                    load_stage(stage0 + t * STAGE_BYTES, c + 2,
                               x, w, wbase, s_tok, tid, FULLB(t));
                }

                uint32_t Af[2][4];
                #pragma unroll
                for (int mt = 0; mt < 2; mt++) {
                    const uint32_t ao = baseA[mt] +
                        (uint32_t)((ks * 2 + skA) << 4);
                    ldsm_x4(Af[mt], sbuf + ao);   // raw fp32; HW truncates
                }
                const uint32_t bks = sbuf + OFF_B + baseB + (uint32_t)(ks * 32);
                #pragma unroll
                for (int j = 0; j < 4; j++) {
                    uint32_t Bf[4];               // b0,b1 of nt=2j; 2j+1
                    ldsm_x4(Bf, bks + (uint32_t)(j * 16 * BSTRIDE));
                    #pragma unroll
                    for (int mt = 0; mt < 2; mt++) {
                        mma_tf32(acc[mt][2 * j],     Af[mt], Bf[0], Bf[1]);
                        mma_tf32(acc[mt][2 * j + 1], Af[mt], Bf[2], Bf[3]);
                    }
                }
            }

            // advance stage / parity
            cs++;
            if (cs == 3) { cs = 0; cu ^= 1; }
        }

        // epilogue: cancel two-sided truncation bias, then store
        const int g = lane >> 2;
        const int t = lane & 3;
        #pragma unroll
        for (int mt = 0; mt < 2; mt++) {
            const int mBase = wm * 32 + mt * 16;
            const int m0 = mBase + g;
            const int m1 = mBase + g + 8;
            float* r0p = out + (size_t)(row0 + m0) * NDIM + n0 + wn * 64 + 2 * t;
            float* r1p = out + (size_t)(row0 + m1) * NDIM + n0 + wn * 64 + 2 * t;
            #pragma unroll
            for (int nt = 0; nt < 8; nt++) {
                if (m0 < nrows) {
                    float2 v;
                    v.x = acc[mt][nt][0] * OSCALE;
                    v.y = acc[mt][nt][1] * OSCALE;
                    *(float2*)(r0p + nt * 8) = v;
                }
                if (m1 < nrows) {
                    float2 v;
                    v.x = acc[mt][nt][2] * OSCALE;
                    v.y = acc[mt][nt][3] * OSCALE;
                    *(float2*)(r1p + nt * 8) = v;
                }
            }
        }

        jc++;
    }
    #undef FULLB
}

// ---------------------------------------------------------------------------
extern "C" void kernel_launch(void* const* d_in, const int* in_sizes, int n_in,
                              void* d_out, int out_size) {
    const float* x       = (const float*)d_in[0];
    const float* weights = (const float*)d_in[1];
    const int*   scatter = (const int*)d_in[2];
    const int*   splits  = (const int*)d_in[3];
    float*       out     = (float*)d_out;
    (void)in_sizes; (void)n_in; (void)out_size;

    cudaFuncSetAttribute(moe_gemm_tf32,
                         cudaFuncAttributeMaxDynamicSharedMemorySize, SMEM_TOTAL);

    prep_all<<<PREP_GRID, 256>>>(scatter, splits);
    moe_gemm_tf32<<<304, 256, SMEM_TOTAL>>>(x, weights, out);  // 2 CTAs/SM
}